// round 15
// baseline (speedup 1.0000x reference)
#include <cuda_runtime.h>
#include <cuda_fp16.h>
#include <math.h>
#include <stdint.h>

// Problem constants
#define Bn 2
#define Cn 256
#define Hn 96
#define Wn 96
#define HW (Hn*Wn)
#define CGn 64
#define KKn 9
#define KTOT 2304
#define NCHUNK 72           // K chunks of 32

// Output layout
#define OUT_LOGITS 0
#define OUT_BBOX   18432
#define OUT_SHAPE  92160
#define OUT_LOC    129024

// smem strides in HALVES — 40: conflict-free fragment loads (R10-proven)
#define LDAh 40
#define LDBh 40
#define LDCh 160             // corner row stride: 320B (16B-aligned, 64 mod 128)

// ---- conv1 smem layout: 4-deep pipeline (R13) ----
#define C1A0  0              // 128*40*2 = 10240 each
#define C1A1  10240
#define C1A2  20480
#define C1A3  30720
#define C1B0  40960          // 256*40*2 = 20480 each
#define C1B1  61440
#define C1B2  81920
#define C1B3  102400
#define C1RED 122880
#define C1SHV 133120
#define C1TOTAL 134144

// ---- deform smem layout: 128px tile + 2-deep corner staging ----
#define D_A0   0             // 128*40*2 = 10240
#define D_A1   10240
#define D_B0   20480         // 256*40*2 = 20480
#define D_B1   40960
#define D_C0   61440         // 128*320 = 40960
#define D_C1   102400
#define D_RED  143360        // 5*512*4 = 10240
#define D_TOTAL 153600

// Scratch (device globals)
__device__ __half g_x  [Bn*HW*Cn];     // feature NHWC, fp16
__device__ __half g_t  [Bn*HW*Cn];     // conv1 output NHWC, fp16
__device__ float  g_off[Bn*HW*72];
__device__ __half g_w1h[KTOT*Cn];      // [chunk][oc][32], fp16
__device__ __half g_w2h[KTOT*Cn];

// ---------------- helpers ---------------------------------------------------
__device__ __forceinline__ uint32_t smem_u32(const void* p) {
    uint32_t a;
    asm("{ .reg .u64 t; cvta.to.shared.u64 t, %1; cvt.u32.u64 %0, t; }"
        : "=r"(a) : "l"(p));
    return a;
}
__device__ __forceinline__ void mma16(float* d, const uint32_t* a,
                                      uint32_t b0, uint32_t b1) {
    asm volatile(
        "mma.sync.aligned.m16n8k16.row.col.f32.f16.f16.f32 "
        "{%0,%1,%2,%3},{%4,%5,%6,%7},{%8,%9},{%0,%1,%2,%3};"
        : "+f"(d[0]), "+f"(d[1]), "+f"(d[2]), "+f"(d[3])
        : "r"(a[0]), "r"(a[1]), "r"(a[2]), "r"(a[3]), "r"(b0), "r"(b1));
}
#define CPA16(dst, src) \
    asm volatile("cp.async.ca.shared.global [%0], [%1], 16;" \
                 :: "r"(dst), "l"(src))
#define CPA16Z(dst, src, n) \
    asm volatile("cp.async.ca.shared.global [%0], [%1], 16, %2;" \
                 :: "r"(dst), "l"(src), "r"(n))
#define CPA_COMMIT() asm volatile("cp.async.commit_group;")
#define CPA_WAIT0()  asm volatile("cp.async.wait_group 0;")
#define CPA_WAIT1()  asm volatile("cp.async.wait_group 1;")
#define CPA_WAIT2()  asm volatile("cp.async.wait_group 2;")

// ---------------------------------------------------------------------------
// Kernel 1: NCHW -> NHWC transpose of feature, to fp16
// ---------------------------------------------------------------------------
__global__ void k_transpose_feat(const float* __restrict__ x) {
    __shared__ float tile[32][33];
    int b  = blockIdx.z;
    int p0 = blockIdx.x * 32;
    int c0 = blockIdx.y * 32;
    int txi = threadIdx.x, tyi = threadIdx.y;  // 32 x 8
    #pragma unroll
    for (int s = 0; s < 32; s += 8)
        tile[tyi + s][txi] = x[(size_t)(b*Cn + c0 + tyi + s)*HW + p0 + txi];
    __syncthreads();
    #pragma unroll
    for (int s = 0; s < 32; s += 8)
        g_x[(size_t)(b*HW + p0 + tyi + s)*Cn + c0 + txi] =
            __float2half(tile[txi][tyi + s]);
}

// ---------------------------------------------------------------------------
// Kernel 2: weight re-layout into chunked [chunk][oc][32] fp16 tiles
// ---------------------------------------------------------------------------
__global__ void k_prep_w(const float* __restrict__ conv_w,
                         const float* __restrict__ adapt_w) {
    const int n = KTOT*Cn;
    int idx = blockIdx.x * blockDim.x + threadIdx.x;
    if (idx < n) {
        int dk = idx & 31;
        int o  = (idx >> 5) & 255;
        int ch = idx >> 13;
        int tap = ch >> 3;
        int c   = (ch & 7)*32 + dk;
        g_w1h[idx] = __float2half(conv_w[(o*Cn + c)*KKn + tap]);
    } else if (idx < 2*n) {
        int j  = idx - n;
        int dk = j & 31;
        int o  = (j >> 5) & 255;
        int ch = j >> 13;
        int gt = ch >> 1;
        int ci = (ch & 1)*32 + dk;
        int g  = gt / 9, tap = gt % 9;
        g_w2h[j] = __float2half(adapt_w[(o*Cn + g*CGn + ci)*KKn + tap]);
    }
}

// One k16-step, 128px tile (warp 64px x 64oc)
#define MMA_KSTEP(Abuf, Bbuf, ks) {                                            \
    const int k0 = (ks)*16;                                                    \
    uint32_t a[4][4];                                                          \
    _Pragma("unroll")                                                          \
    for (int ma = 0; ma < 4; ++ma) {                                           \
        const __half* ap = &(Abuf)[(wm*64 + ma*16 + g)*LDAh + k0 + 2*t];       \
        a[ma][0] = *(const uint32_t*)(ap);                                     \
        a[ma][1] = *(const uint32_t*)(ap + 8*LDAh);                            \
        a[ma][2] = *(const uint32_t*)(ap + 8);                                 \
        a[ma][3] = *(const uint32_t*)(ap + 8*LDAh + 8);                        \
    }                                                                          \
    _Pragma("unroll")                                                          \
    for (int na = 0; na < 8; ++na) {                                           \
        const __half* bp = &(Bbuf)[(wn*64 + na*8 + g)*LDBh + k0 + 2*t];        \
        const uint32_t b0 = *(const uint32_t*)(bp);                            \
        const uint32_t b1 = *(const uint32_t*)(bp + 8);                        \
        mma16(d[0][na], a[0], b0, b1);                                         \
        mma16(d[1][na], a[1], b0, b1);                                         \
        mma16(d[2][na], a[2], b0, b1);                                         \
        mma16(d[3][na], a[3], b0, b1);                                         \
    }                                                                          \
}

#define MMA_CHUNK(Abuf, Bbuf) MMA_KSTEP(Abuf, Bbuf, 0) MMA_KSTEP(Abuf, Bbuf, 1)

// ---------------------------------------------------------------------------
// Kernel 3: conv3x3 via mma.sync fp16, 4-deep cp.async pipeline (R13, WIN)
// ---------------------------------------------------------------------------
__global__ void __launch_bounds__(256, 1)
k_conv1_mma(const float* __restrict__ conv_b_,
            const float* __restrict__ loc_w,  const float* __restrict__ loc_b,
            const float* __restrict__ shape_w,const float* __restrict__ shape_b,
            const float* __restrict__ offset_w,
            float* __restrict__ out) {
    extern __shared__ __align__(128) char smem[];
    __half* AsmP[4] = {(__half*)(smem + C1A0), (__half*)(smem + C1A1),
                       (__half*)(smem + C1A2), (__half*)(smem + C1A3)};
    __half* BsmP[4] = {(__half*)(smem + C1B0), (__half*)(smem + C1B1),
                       (__half*)(smem + C1B2), (__half*)(smem + C1B3)};
    float*  red  = (float*)(smem + C1RED);
    float*  shv  = (float*)(smem + C1SHV);

    const int tid = threadIdx.x, wid = tid >> 5, lane = tid & 31;
    const int g = lane >> 2, t = lane & 3;
    const int wm = wid & 1, wn = wid >> 1;

    const int tt = blockIdx.x;
    const int b  = blockIdx.y;
    const int y0 = (tt / 6) * 8, x0 = (tt % 6) * 16;

    const int pB = tid >> 2, qS = tid & 3;

    float d[4][8][4];
    #pragma unroll
    for (int i = 0; i < 4; ++i)
        #pragma unroll
        for (int j = 0; j < 8; ++j)
            #pragma unroll
            for (int k = 0; k < 4; ++k) d[i][j][k] = 0.f;

    const uint32_t daOff = (uint32_t)(pB*LDAh + qS*8)*2;
    const uint32_t dbOff = (uint32_t)(tid*LDBh)*2;
    const uint32_t daP[4] = {smem_u32(AsmP[0]) + daOff, smem_u32(AsmP[1]) + daOff,
                             smem_u32(AsmP[2]) + daOff, smem_u32(AsmP[3]) + daOff};
    const uint32_t dbP[4] = {smem_u32(BsmP[0]) + dbOff, smem_u32(BsmP[1]) + dbOff,
                             smem_u32(BsmP[2]) + dbOff, smem_u32(BsmP[3]) + dbOff};

    auto stage = [&](int c, uint32_t da, uint32_t db) {
        const int tap = c >> 3, cin0 = (c & 7) << 5;
        const int dy = tap/3 - 1, dx = tap%3 - 1;
        #pragma unroll
        for (int ph = 0; ph < 2; ++ph) {
            const int pS = ph*64 + pB;
            const int yy = y0 + (pS >> 4) + dy, xx = x0 + (pS & 15) + dx;
            const bool ok = (yy >= 0 && yy < Hn && xx >= 0 && xx < Wn);
            const __half* src = ok
                ? &g_x[((size_t)((b*Hn + yy)*Wn + xx))*Cn + cin0 + qS*8] : g_x;
            const uint32_t nb = ok ? 16u : 0u;
            CPA16Z(da + (uint32_t)(ph*64*LDAh)*2, src, nb);
        }
        const __half* ws = &g_w1h[(size_t)c*8192 + tid*32];
        #pragma unroll
        for (int q = 0; q < 4; ++q) CPA16(db + q*16, ws + q*8);
        CPA_COMMIT();
    };

    stage(0, daP[0], dbP[0]);
    stage(1, daP[1], dbP[1]);
    stage(2, daP[2], dbP[2]);

    #pragma unroll 1
    for (int c = 0; c < NCHUNK; c += 4) {
        CPA_WAIT2(); __syncthreads();
        MMA_CHUNK(AsmP[0], BsmP[0]);
        if (c + 3 < NCHUNK) stage(c + 3, daP[3], dbP[3]);

        CPA_WAIT2(); __syncthreads();
        MMA_CHUNK(AsmP[1], BsmP[1]);
        if (c + 4 < NCHUNK) stage(c + 4, daP[0], dbP[0]);

        CPA_WAIT2(); __syncthreads();
        MMA_CHUNK(AsmP[2], BsmP[2]);
        if (c + 5 < NCHUNK) stage(c + 5, daP[1], dbP[1]);

        CPA_WAIT2(); __syncthreads();
        MMA_CHUNK(AsmP[3], BsmP[3]);
        if (c + 6 < NCHUNK) stage(c + 6, daP[2], dbP[2]);
    }
    __syncthreads();

    // ---- epilogue ----
    float P0[8], P1[8], P2[8];
    #pragma unroll
    for (int s = 0; s < 8; ++s) { P0[s] = 0.f; P1[s] = 0.f; P2[s] = 0.f; }

    #pragma unroll
    for (int ma = 0; ma < 4; ++ma)
        #pragma unroll
        for (int na = 0; na < 8; ++na)
            #pragma unroll
            for (int ci = 0; ci < 4; ++ci) {
                const int oc = wn*64 + na*8 + 2*t + (ci & 1);
                const int slot = ma*2 + (ci >> 1);
                float v = fmaxf(d[ma][na][ci] + conv_b_[oc], 0.f);
                d[ma][na][ci] = v;
                P0[slot] += v * loc_w[oc];
                P1[slot] += v * shape_w[oc];
                P2[slot] += v * shape_w[Cn + oc];
            }
    #pragma unroll
    for (int s = 0; s < 8; ++s) {
        P0[s] += __shfl_xor_sync(0xffffffffu, P0[s], 1);
        P0[s] += __shfl_xor_sync(0xffffffffu, P0[s], 2);
        P1[s] += __shfl_xor_sync(0xffffffffu, P1[s], 1);
        P1[s] += __shfl_xor_sync(0xffffffffu, P1[s], 2);
        P2[s] += __shfl_xor_sync(0xffffffffu, P2[s], 2);
        P2[s] += __shfl_xor_sync(0xffffffffu, P2[s], 1);
    }
    if (t == 0) {
        #pragma unroll
        for (int s = 0; s < 8; ++s) {
            const int row = wm*64 + (s >> 1)*16 + g + (s & 1)*8;
            red[0*512 + row*4 + wn] = P0[s];
            red[1*512 + row*4 + wn] = P1[s];
            red[2*512 + row*4 + wn] = P2[s];
        }
    }
    __syncthreads();

    if (tid < 128) {
        const int px = tid;
        float sl = 0.f, s0 = 0.f, s1 = 0.f;
        #pragma unroll
        for (int w = 0; w < 4; ++w) {
            sl += red[0*512 + px*4 + w];
            s0 += red[1*512 + px*4 + w];
            s1 += red[2*512 + px*4 + w];
        }
        const int y = y0 + (px >> 4), xg = x0 + (px & 15);
        const int pix = y*Wn + xg;
        out[OUT_LOC + b*HW + pix] = sl + loc_b[0];
        const float a0 = s0 + shape_b[0];
        const float a1 = s1 + shape_b[1];
        out[OUT_SHAPE + (b*2 + 0)*HW + pix] = a0;
        out[OUT_SHAPE + (b*2 + 1)*HW + pix] = a1;
        shv[px*2 + 0] = a0;
        shv[px*2 + 1] = a1;
    }
    __syncthreads();

    for (int idx = tid; idx < 128*72; idx += 256) {
        const int p = idx / 72, j = idx % 72;
        const int y = y0 + (p >> 4), xg = x0 + (p & 15);
        float v = shv[p*2]*offset_w[j*2] + shv[p*2+1]*offset_w[j*2+1];
        g_off[((size_t)((b*Hn + y)*Wn + xg))*72 + j] = v;
    }

    #pragma unroll
    for (int ma = 0; ma < 4; ++ma) {
        const int row0 = wm*64 + ma*16 + g;
        const int pix0 = (b*Hn + y0 + (row0 >> 4))*Wn + x0 + (row0 & 15);
        const int row1 = row0 + 8;
        const int pix1 = (b*Hn + y0 + (row1 >> 4))*Wn + x0 + (row1 & 15);
        #pragma unroll
        for (int na = 0; na < 8; ++na) {
            const int col = wn*64 + na*8 + 2*t;
            *(__half2*)&g_t[(size_t)pix0*Cn + col] =
                __floats2half2_rn(d[ma][na][0], d[ma][na][1]);
            *(__half2*)&g_t[(size_t)pix1*Cn + col] =
                __floats2half2_rn(d[ma][na][2], d[ma][na][3]);
        }
    }
}

// ---------------------------------------------------------------------------
// Kernel 4: deformable conv, 128px tile, 2-deep cp.async corner staging
// ---------------------------------------------------------------------------
__global__ void __launch_bounds__(256, 1)
k_deform_mma(const float* __restrict__ cls_w, const float* __restrict__ cls_b,
             const float* __restrict__ bbox_w, const float* __restrict__ bbox_b,
             float* __restrict__ out) {
    extern __shared__ __align__(128) char smem[];
    __half* Asm0 = (__half*)(smem + D_A0);
    __half* Asm1 = (__half*)(smem + D_A1);
    __half* Bsm0 = (__half*)(smem + D_B0);
    __half* Bsm1 = (__half*)(smem + D_B1);
    __half* Csm0 = (__half*)(smem + D_C0);
    __half* Csm1 = (__half*)(smem + D_C1);
    float*  red  = (float*)(smem + D_RED);

    const int tid = threadIdx.x, wid = tid >> 5, lane = tid & 31;
    const int g = lane >> 2, t = lane & 3;
    const int wm = wid & 1, wn = wid >> 1;

    const int tt = blockIdx.x;
    const int b  = blockIdx.y;
    const int y0 = (tt / 6) * 8, x0 = (tt % 6) * 16;

    const int pB = tid >> 2, qS = tid & 3;
    int   yP[2], xP[2], pixb[2];
    #pragma unroll
    for (int ph = 0; ph < 2; ++ph) {
        const int pS = ph*64 + pB;
        yP[ph] = y0 + (pS >> 4);
        xP[ph] = x0 + (pS & 15);
        pixb[ph] = (b*Hn + yP[ph])*Wn + xP[ph];
    }

    float d[4][8][4];
    #pragma unroll
    for (int i = 0; i < 4; ++i)
        #pragma unroll
        for (int j = 0; j < 8; ++j)
            #pragma unroll
            for (int k = 0; k < 4; ++k) d[i][j][k] = 0.f;

    const uint32_t dbOff = (uint32_t)(tid*LDBh)*2;
    const uint32_t db0 = smem_u32(Bsm0) + dbOff, db1 = smem_u32(Bsm1) + dbOff;
    // corner staging dst (cp.async), per buffer per phase
    const uint32_t ccOff0 = (uint32_t)((0*64 + pB)*LDCh + qS*8)*2;
    const uint32_t ccOff1 = (uint32_t)((1*64 + pB)*LDCh + qS*8)*2;
    const uint32_t cd0[2] = {smem_u32(Csm0) + ccOff0, smem_u32(Csm0) + ccOff1};
    const uint32_t cd1[2] = {smem_u32(Csm1) + ccOff0, smem_u32(Csm1) + ccOff1};

    // meta: two gt sets (indexed by gt parity)
    int   myi[2][2], mxi[2][2];
    float mwy[2][2], mwx[2][2];
    float2 offT0, offT1;

    auto calc_meta = [&](int s, int gt, float2 o0, float2 o1) {
        const int gg = gt / 9, tap = gt - gg*9;
        const int dy = tap/3 - 1, dx = tap%3 - 1;
        #pragma unroll
        for (int ph = 0; ph < 2; ++ph) {
            const float2 off = ph ? o1 : o0;
            const float pyf = (float)(yP[ph] + dy) + off.x;
            const float pxf = (float)(xP[ph] + dx) + off.y;
            const float y0f = floorf(pyf), x0f = floorf(pxf);
            myi[s][ph] = (int)y0f;
            mxi[s][ph] = (int)x0f;
            mwy[s][ph] = pyf - y0f;
            mwx[s][ph] = pxf - x0f;
        }
    };

    auto gather = [&](int cc, const uint32_t* cd) {
        const int gt = cc >> 1, s = gt & 1, gg = gt / 9;
        const int chb = gg*CGn + (cc & 1)*32 + qS*8;
        #pragma unroll
        for (int ph = 0; ph < 2; ++ph) {
            const int yi = myi[s][ph], xi = mxi[s][ph];
            #pragma unroll
            for (int cy = 0; cy < 2; ++cy)
                #pragma unroll
                for (int cx = 0; cx < 2; ++cx) {
                    const int k = cy*2 + cx;
                    const int yc = min(max(yi + cy, 0), Hn - 1);
                    const int xc = min(max(xi + cx, 0), Wn - 1);
                    const __half* src =
                        &g_t[((size_t)((b*Hn + yc)*Wn + xc))*Cn + chb];
                    CPA16(cd[ph] + k*64, src);
                }
        }
        CPA_COMMIT();
    };

    auto combine = [&](int cc, const __half* Cbuf, __half* Abuf) {
        const int gt = cc >> 1, s = gt & 1;
        #pragma unroll
        for (int ph = 0; ph < 2; ++ph) {
            const int yi = myi[s][ph], xi = mxi[s][ph];
            const float wy = mwy[s][ph], wx = mwx[s][ph];
            float w[4];
            #pragma unroll
            for (int cy = 0; cy < 2; ++cy)
                #pragma unroll
                for (int cx = 0; cx < 2; ++cx) {
                    const int k = cy*2 + cx;
                    const bool valid = (yi+cy >= 0 && yi+cy < Hn &&
                                        xi+cx >= 0 && xi+cx < Wn);
                    const float wv = (cy ? wy : 1.f - wy) * (cx ? wx : 1.f - wx);
                    w[k] = valid ? wv : 0.f;
                }
            const __half* crow = Cbuf + (ph*64 + pB)*LDCh + qS*8;
            float r[8];
            #pragma unroll
            for (int j = 0; j < 8; ++j) r[j] = 0.f;
            #pragma unroll
            for (int k = 0; k < 4; ++k) {
                const uint4 uu = *(const uint4*)(crow + k*32);
                const __half2* h = (const __half2*)&uu;
                #pragma unroll
                for (int j = 0; j < 4; ++j) {
                    const float2 v = __half22float2(h[j]);
                    r[2*j]   += w[k] * v.x;
                    r[2*j+1] += w[k] * v.y;
                }
            }
            __half2 o[4];
            #pragma unroll
            for (int j = 0; j < 4; ++j)
                o[j] = __floats2half2_rn(r[2*j], r[2*j+1]);
            *(uint4*)&Abuf[(ph*64 + pB)*LDAh + qS*8] = *(uint4*)o;
        }
    };

#define STAGE_B2(cc, db) {                                                     \
    const __half* ws = &g_w2h[(size_t)(cc)*8192 + tid*32];                     \
    _Pragma("unroll")                                                          \
    for (int q = 0; q < 4; ++q) CPA16((db) + q*16, ws + q*8);                  \
    CPA_COMMIT();                                                              \
}

    // ---- prologue ----
    float2 o0 = *(const float2*)&g_off[(size_t)pixb[0]*72];
    float2 o1 = *(const float2*)&g_off[(size_t)pixb[1]*72];
    calc_meta(0, 0, o0, o1);
    offT0 = *(const float2*)&g_off[(size_t)pixb[0]*72 + 2];
    offT1 = *(const float2*)&g_off[(size_t)pixb[1]*72 + 2];
    calc_meta(1, 1, offT0, offT1);
    offT0 = *(const float2*)&g_off[(size_t)pixb[0]*72 + 4];
    offT1 = *(const float2*)&g_off[(size_t)pixb[1]*72 + 4];
    STAGE_B2(0, db0);
    gather(0, cd0);
    gather(1, cd1);
    CPA_WAIT0();
    __syncthreads();           // corners visible to all (each thread combines own data, but keep safe)
    combine(0, Csm0, Asm0);
    __syncthreads();

    #pragma unroll 1
    for (int c = 0; c < NCHUNK; c += 2) {
        // ---- even half: MMA chunk c (A0,B0) ----
        const bool hb = (c + 1 < NCHUNK);
        const bool hg = (c + 2 < NCHUNK);
        if (c > 0 && hg) {
            const int gtn = (c + 2) >> 1;
            calc_meta(gtn & 1, gtn, offT0, offT1);
            if (gtn + 1 < 36) {
                offT0 = *(const float2*)&g_off[(size_t)pixb[0]*72 + (gtn+1)*2];
                offT1 = *(const float2*)&g_off[(size_t)pixb[1]*72 + (gtn+1)*2];
            }
        }
        if (hb) STAGE_B2(c + 1, db1);
        if (hg) gather(c + 2, cd0);
        MMA_CHUNK(Asm0, Bsm0);
        if (hg) { CPA_WAIT1(); } else { CPA_WAIT0(); }
        if (hb) combine(c + 1, Csm1, Asm1);
        __syncthreads();

        // ---- odd half: MMA chunk c+1 (A1,B1) ----
        if (hb) {
            const bool hb2 = (c + 2 < NCHUNK);
            const bool hg2 = (c + 3 < NCHUNK);
            if (hb2) STAGE_B2(c + 2, db0);
            if (hg2) gather(c + 3, cd1);
            MMA_CHUNK(Asm1, Bsm1);
            if (hg2) { CPA_WAIT1(); } else { CPA_WAIT0(); }
            if (hb2) combine(c + 2, Csm0, Asm0);
            __syncthreads();
        }
    }

    // ---- epilogue: relu + cls/bbox head partials -----------------------
    float P[5][8];
    #pragma unroll
    for (int h = 0; h < 5; ++h)
        #pragma unroll
        for (int s = 0; s < 8; ++s) P[h][s] = 0.f;

    #pragma unroll
    for (int ma = 0; ma < 4; ++ma)
        #pragma unroll
        for (int na = 0; na < 8; ++na)
            #pragma unroll
            for (int ci = 0; ci < 4; ++ci) {
                const int oc = wn*64 + na*8 + 2*t + (ci & 1);
                const int slot = ma*2 + (ci >> 1);
                const float v = fmaxf(d[ma][na][ci], 0.f);
                P[0][slot] += v * cls_w[oc];
                P[1][slot] += v * bbox_w[oc];
                P[2][slot] += v * bbox_w[Cn + oc];
                P[3][slot] += v * bbox_w[2*Cn + oc];
                P[4][slot] += v * bbox_w[3*Cn + oc];
            }
    #pragma unroll
    for (int h = 0; h < 5; ++h)
        #pragma unroll
        for (int s = 0; s < 8; ++s) {
            P[h][s] += __shfl_xor_sync(0xffffffffu, P[h][s], 1);
            P[h][s] += __shfl_xor_sync(0xffffffffu, P[h][s], 2);
        }
    if (t == 0) {
        #pragma unroll
        for (int s = 0; s < 8; ++s) {
            const int row = wm*64 + (s >> 1)*16 + g + (s & 1)*8;
            #pragma unroll
            for (int h = 0; h < 5; ++h)
                red[h*512 + row*4 + wn] = P[h][s];
        }
    }
    __syncthreads();

    if (tid < 128) {
        const int px = tid;
        float s[5] = {0.f, 0.f, 0.f, 0.f, 0.f};
        #pragma unroll
        for (int h = 0; h < 5; ++h)
            #pragma unroll
            for (int w = 0; w < 4; ++w)
                s[h] += red[h*512 + px*4 + w];
        const int y = y0 + (px >> 4), xg = x0 + (px & 15);
        const int pix = y*Wn + xg;
        out[OUT_LOGITS + b*HW + pix]        = s[0] + cls_b[0];
        out[OUT_BBOX + (b*4 + 0)*HW + pix]  = s[1] + bbox_b[0];
        out[OUT_BBOX + (b*4 + 1)*HW + pix]  = s[2] + bbox_b[1];
        out[OUT_BBOX + (b*4 + 2)*HW + pix]  = s[3] + bbox_b[2];
        out[OUT_BBOX + (b*4 + 3)*HW + pix]  = s[4] + bbox_b[3];
    }
}

// ---------------------------------------------------------------------------
extern "C" void kernel_launch(void* const* d_in, const int* in_sizes, int n_in,
                              void* d_out, int out_size) {
    const float* feature  = (const float*)d_in[0];
    const float* conv_w   = (const float*)d_in[1];
    const float* conv_b   = (const float*)d_in[2];
    const float* loc_w    = (const float*)d_in[3];
    const float* loc_b    = (const float*)d_in[4];
    const float* shape_w  = (const float*)d_in[5];
    const float* shape_b  = (const float*)d_in[6];
    const float* offset_w = (const float*)d_in[7];
    const float* adapt_w  = (const float*)d_in[8];
    const float* cls_w    = (const float*)d_in[9];
    const float* cls_b    = (const float*)d_in[10];
    const float* bbox_w   = (const float*)d_in[11];
    const float* bbox_b   = (const float*)d_in[12];
    float* out = (float*)d_out;

    cudaFuncSetAttribute(k_conv1_mma,
        cudaFuncAttributeMaxDynamicSharedMemorySize, C1TOTAL);
    cudaFuncSetAttribute(k_deform_mma,
        cudaFuncAttributeMaxDynamicSharedMemorySize, D_TOTAL);

    k_transpose_feat<<<dim3(HW/32, Cn/32, Bn), dim3(32, 8)>>>(feature);
    k_prep_w<<<(2*KTOT*Cn + 255)/256, 256>>>(conv_w, adapt_w);
    k_conv1_mma<<<dim3(72, Bn), 256, C1TOTAL>>>(conv_b, loc_w, loc_b,
                                                shape_w, shape_b,
                                                offset_w, out);
    k_deform_mma<<<dim3(72, Bn), 256, D_TOTAL>>>(cls_w, cls_b,
                                                 bbox_w, bbox_b, out);
}

// round 16
// speedup vs baseline: 1.1784x; 1.1784x over previous
#include <cuda_runtime.h>
#include <cuda_fp16.h>
#include <math.h>
#include <stdint.h>

// Problem constants
#define Bn 2
#define Cn 256
#define Hn 96
#define Wn 96
#define HW (Hn*Wn)
#define CGn 64
#define KKn 9
#define KTOT 2304
#define NCHUNK 72           // K chunks of 32

// Output layout
#define OUT_LOGITS 0
#define OUT_BBOX   18432
#define OUT_SHAPE  92160
#define OUT_LOC    129024

// smem strides in HALVES — 40: conflict-free fragment loads (R10-proven)
#define LDAh 40
#define LDBh 40

// ---- conv1 smem layout: 4-deep pipeline (R13) ----
#define C1A0  0              // 128*40*2 = 10240 each
#define C1A1  10240
#define C1A2  20480
#define C1A3  30720
#define C1B0  40960          // 256*40*2 = 20480 each
#define C1B1  61440
#define C1B2  81920
#define C1B3  102400
#define C1RED 122880         // 3*512*4 = 6144
#define C1TOTAL 129024

// ---- deform smem layout: R13 + offset_w cache ----
#define SM_A0   0            // 128*40*2 = 10240
#define SM_A1   10240
#define SM_B0   20480        // 256*40*2 = 20480
#define SM_B1   40960
#define SM_RED  61440        // 5*512*4  = 10240
#define SM_OW   71680        // 144*4 = 576
#define SM_TOTAL 72704

// Scratch (device globals)
__device__ __half g_x  [Bn*HW*Cn];     // feature NHWC, fp16
__device__ __half g_t  [Bn*HW*Cn];     // conv1 output NHWC, fp16
__device__ float  g_sh [Bn*HW*2];      // shape_pred per pixel (s0,s1)
__device__ __half g_w1h[KTOT*Cn];      // [chunk][oc][32], fp16
__device__ __half g_w2h[KTOT*Cn];

// ---------------- helpers ---------------------------------------------------
__device__ __forceinline__ uint32_t smem_u32(const void* p) {
    uint32_t a;
    asm("{ .reg .u64 t; cvta.to.shared.u64 t, %1; cvt.u32.u64 %0, t; }"
        : "=r"(a) : "l"(p));
    return a;
}
__device__ __forceinline__ void mma16(float* d, const uint32_t* a,
                                      uint32_t b0, uint32_t b1) {
    asm volatile(
        "mma.sync.aligned.m16n8k16.row.col.f32.f16.f16.f32 "
        "{%0,%1,%2,%3},{%4,%5,%6,%7},{%8,%9},{%0,%1,%2,%3};"
        : "+f"(d[0]), "+f"(d[1]), "+f"(d[2]), "+f"(d[3])
        : "r"(a[0]), "r"(a[1]), "r"(a[2]), "r"(a[3]), "r"(b0), "r"(b1));
}
#define CPA16(dst, src) \
    asm volatile("cp.async.ca.shared.global [%0], [%1], 16;" \
                 :: "r"(dst), "l"(src))
#define CPA16Z(dst, src, n) \
    asm volatile("cp.async.ca.shared.global [%0], [%1], 16, %2;" \
                 :: "r"(dst), "l"(src), "r"(n))
#define CPA_COMMIT() asm volatile("cp.async.commit_group;")
#define CPA_WAIT0()  asm volatile("cp.async.wait_group 0;")
#define CPA_WAIT2()  asm volatile("cp.async.wait_group 2;")

// ---------------------------------------------------------------------------
// Kernel 1: merged prep — transpose feature (blocks 0..4607) + weight
//           re-layout (blocks 4608..9215)
// ---------------------------------------------------------------------------
__global__ void k_prep_all(const float* __restrict__ x,
                           const float* __restrict__ conv_w,
                           const float* __restrict__ adapt_w) {
    __shared__ float tile[32][33];
    const int tid = threadIdx.x;
    if (blockIdx.x < 4608) {
        // transpose: bid -> (b, pixel block, channel block)
        const int bid = blockIdx.x;
        const int b  = bid / 2304;
        const int r  = bid % 2304;
        const int p0 = (r >> 3) * 32;
        const int c0 = (r & 7) * 32;
        const int txi = tid & 31, tyi = tid >> 5;
        #pragma unroll
        for (int s = 0; s < 32; s += 8)
            tile[tyi + s][txi] = x[(size_t)(b*Cn + c0 + tyi + s)*HW + p0 + txi];
        __syncthreads();
        #pragma unroll
        for (int s = 0; s < 32; s += 8)
            g_x[(size_t)(b*HW + p0 + tyi + s)*Cn + c0 + txi] =
                __float2half(tile[txi][tyi + s]);
    } else {
        const int n = KTOT*Cn;
        int idx = (blockIdx.x - 4608) * 256 + tid;
        if (idx < n) {
            int dk = idx & 31;
            int o  = (idx >> 5) & 255;
            int ch = idx >> 13;
            int tap = ch >> 3;
            int c   = (ch & 7)*32 + dk;
            g_w1h[idx] = __float2half(conv_w[(o*Cn + c)*KKn + tap]);
        } else if (idx < 2*n) {
            int j  = idx - n;
            int dk = j & 31;
            int o  = (j >> 5) & 255;
            int ch = j >> 13;
            int gt = ch >> 1;
            int ci = (ch & 1)*32 + dk;
            int g  = gt / 9, tap = gt % 9;
            g_w2h[j] = __float2half(adapt_w[(o*Cn + g*CGn + ci)*KKn + tap]);
        }
    }
}

// One k16-step, 128px tile (warp 64px x 64oc)
#define MMA_KSTEP(Abuf, Bbuf, ks) {                                            \
    const int k0 = (ks)*16;                                                    \
    uint32_t a[4][4];                                                          \
    _Pragma("unroll")                                                          \
    for (int ma = 0; ma < 4; ++ma) {                                           \
        const __half* ap = &(Abuf)[(wm*64 + ma*16 + g)*LDAh + k0 + 2*t];       \
        a[ma][0] = *(const uint32_t*)(ap);                                     \
        a[ma][1] = *(const uint32_t*)(ap + 8*LDAh);                            \
        a[ma][2] = *(const uint32_t*)(ap + 8);                                 \
        a[ma][3] = *(const uint32_t*)(ap + 8*LDAh + 8);                        \
    }                                                                          \
    _Pragma("unroll")                                                          \
    for (int na = 0; na < 8; ++na) {                                           \
        const __half* bp = &(Bbuf)[(wn*64 + na*8 + g)*LDBh + k0 + 2*t];        \
        const uint32_t b0 = *(const uint32_t*)(bp);                            \
        const uint32_t b1 = *(const uint32_t*)(bp + 8);                        \
        mma16(d[0][na], a[0], b0, b1);                                         \
        mma16(d[1][na], a[1], b0, b1);                                         \
        mma16(d[2][na], a[2], b0, b1);                                         \
        mma16(d[3][na], a[3], b0, b1);                                         \
    }                                                                          \
}

#define MMA_CHUNK(Abuf, Bbuf) MMA_KSTEP(Abuf, Bbuf, 0) MMA_KSTEP(Abuf, Bbuf, 1)

// ---------------------------------------------------------------------------
// Kernel 3: conv3x3 via mma.sync fp16, 4-deep cp.async pipeline (R13, WIN)
//           heads fused; writes g_sh instead of the 72-ch offset field
// ---------------------------------------------------------------------------
__global__ void __launch_bounds__(256, 1)
k_conv1_mma(const float* __restrict__ conv_b_,
            const float* __restrict__ loc_w,  const float* __restrict__ loc_b,
            const float* __restrict__ shape_w,const float* __restrict__ shape_b,
            float* __restrict__ out) {
    extern __shared__ __align__(128) char smem[];
    __half* AsmP[4] = {(__half*)(smem + C1A0), (__half*)(smem + C1A1),
                       (__half*)(smem + C1A2), (__half*)(smem + C1A3)};
    __half* BsmP[4] = {(__half*)(smem + C1B0), (__half*)(smem + C1B1),
                       (__half*)(smem + C1B2), (__half*)(smem + C1B3)};
    float*  red  = (float*)(smem + C1RED);

    const int tid = threadIdx.x, wid = tid >> 5, lane = tid & 31;
    const int g = lane >> 2, t = lane & 3;
    const int wm = wid & 1, wn = wid >> 1;

    const int tt = blockIdx.x;
    const int b  = blockIdx.y;
    const int y0 = (tt / 6) * 8, x0 = (tt % 6) * 16;

    const int pB = tid >> 2, qS = tid & 3;

    float d[4][8][4];
    #pragma unroll
    for (int i = 0; i < 4; ++i)
        #pragma unroll
        for (int j = 0; j < 8; ++j)
            #pragma unroll
            for (int k = 0; k < 4; ++k) d[i][j][k] = 0.f;

    const uint32_t daOff = (uint32_t)(pB*LDAh + qS*8)*2;
    const uint32_t dbOff = (uint32_t)(tid*LDBh)*2;
    const uint32_t daP[4] = {smem_u32(AsmP[0]) + daOff, smem_u32(AsmP[1]) + daOff,
                             smem_u32(AsmP[2]) + daOff, smem_u32(AsmP[3]) + daOff};
    const uint32_t dbP[4] = {smem_u32(BsmP[0]) + dbOff, smem_u32(BsmP[1]) + dbOff,
                             smem_u32(BsmP[2]) + dbOff, smem_u32(BsmP[3]) + dbOff};

    auto stage = [&](int c, uint32_t da, uint32_t db) {
        const int tap = c >> 3, cin0 = (c & 7) << 5;
        const int dy = tap/3 - 1, dx = tap%3 - 1;
        #pragma unroll
        for (int ph = 0; ph < 2; ++ph) {
            const int pS = ph*64 + pB;
            const int yy = y0 + (pS >> 4) + dy, xx = x0 + (pS & 15) + dx;
            const bool ok = (yy >= 0 && yy < Hn && xx >= 0 && xx < Wn);
            const __half* src = ok
                ? &g_x[((size_t)((b*Hn + yy)*Wn + xx))*Cn + cin0 + qS*8] : g_x;
            const uint32_t nb = ok ? 16u : 0u;
            CPA16Z(da + (uint32_t)(ph*64*LDAh)*2, src, nb);
        }
        const __half* ws = &g_w1h[(size_t)c*8192 + tid*32];
        #pragma unroll
        for (int q = 0; q < 4; ++q) CPA16(db + q*16, ws + q*8);
        CPA_COMMIT();
    };

    stage(0, daP[0], dbP[0]);
    stage(1, daP[1], dbP[1]);
    stage(2, daP[2], dbP[2]);

    #pragma unroll 1
    for (int c = 0; c < NCHUNK; c += 4) {
        CPA_WAIT2(); __syncthreads();
        MMA_CHUNK(AsmP[0], BsmP[0]);
        if (c + 3 < NCHUNK) stage(c + 3, daP[3], dbP[3]);

        CPA_WAIT2(); __syncthreads();
        MMA_CHUNK(AsmP[1], BsmP[1]);
        if (c + 4 < NCHUNK) stage(c + 4, daP[0], dbP[0]);

        CPA_WAIT2(); __syncthreads();
        MMA_CHUNK(AsmP[2], BsmP[2]);
        if (c + 5 < NCHUNK) stage(c + 5, daP[1], dbP[1]);

        CPA_WAIT2(); __syncthreads();
        MMA_CHUNK(AsmP[3], BsmP[3]);
        if (c + 6 < NCHUNK) stage(c + 6, daP[2], dbP[2]);
    }
    __syncthreads();

    // ---- epilogue: bias + relu, heads, g_t ----
    float P0[8], P1[8], P2[8];
    #pragma unroll
    for (int s = 0; s < 8; ++s) { P0[s] = 0.f; P1[s] = 0.f; P2[s] = 0.f; }

    #pragma unroll
    for (int ma = 0; ma < 4; ++ma)
        #pragma unroll
        for (int na = 0; na < 8; ++na)
            #pragma unroll
            for (int ci = 0; ci < 4; ++ci) {
                const int oc = wn*64 + na*8 + 2*t + (ci & 1);
                const int slot = ma*2 + (ci >> 1);
                float v = fmaxf(d[ma][na][ci] + conv_b_[oc], 0.f);
                d[ma][na][ci] = v;
                P0[slot] += v * loc_w[oc];
                P1[slot] += v * shape_w[oc];
                P2[slot] += v * shape_w[Cn + oc];
            }
    #pragma unroll
    for (int s = 0; s < 8; ++s) {
        P0[s] += __shfl_xor_sync(0xffffffffu, P0[s], 1);
        P0[s] += __shfl_xor_sync(0xffffffffu, P0[s], 2);
        P1[s] += __shfl_xor_sync(0xffffffffu, P1[s], 1);
        P1[s] += __shfl_xor_sync(0xffffffffu, P1[s], 2);
        P2[s] += __shfl_xor_sync(0xffffffffu, P2[s], 2);
        P2[s] += __shfl_xor_sync(0xffffffffu, P2[s], 1);
    }
    if (t == 0) {
        #pragma unroll
        for (int s = 0; s < 8; ++s) {
            const int row = wm*64 + (s >> 1)*16 + g + (s & 1)*8;
            red[0*512 + row*4 + wn] = P0[s];
            red[1*512 + row*4 + wn] = P1[s];
            red[2*512 + row*4 + wn] = P2[s];
        }
    }
    __syncthreads();

    if (tid < 128) {
        const int px = tid;
        float sl = 0.f, s0 = 0.f, s1 = 0.f;
        #pragma unroll
        for (int w = 0; w < 4; ++w) {
            sl += red[0*512 + px*4 + w];
            s0 += red[1*512 + px*4 + w];
            s1 += red[2*512 + px*4 + w];
        }
        const int y = y0 + (px >> 4), xg = x0 + (px & 15);
        const int pix = y*Wn + xg;
        out[OUT_LOC + b*HW + pix] = sl + loc_b[0];
        const float a0 = s0 + shape_b[0];
        const float a1 = s1 + shape_b[1];
        out[OUT_SHAPE + (b*2 + 0)*HW + pix] = a0;
        out[OUT_SHAPE + (b*2 + 1)*HW + pix] = a1;
        *(float2*)&g_sh[((size_t)(b*HW + pix))*2] = make_float2(a0, a1);
    }

    // g_t: direct scattered half2 stores from accumulators
    #pragma unroll
    for (int ma = 0; ma < 4; ++ma) {
        const int row0 = wm*64 + ma*16 + g;
        const int pix0 = (b*Hn + y0 + (row0 >> 4))*Wn + x0 + (row0 & 15);
        const int row1 = row0 + 8;
        const int pix1 = (b*Hn + y0 + (row1 >> 4))*Wn + x0 + (row1 & 15);
        #pragma unroll
        for (int na = 0; na < 8; ++na) {
            const int col = wn*64 + na*8 + 2*t;
            *(__half2*)&g_t[(size_t)pix0*Cn + col] =
                __floats2half2_rn(d[ma][na][0], d[ma][na][1]);
            *(__half2*)&g_t[(size_t)pix1*Cn + col] =
                __floats2half2_rn(d[ma][na][2], d[ma][na][3]);
        }
    }
}

// ---------------------------------------------------------------------------
// Kernel 4: deformable conv (R13 mainloop), offsets reconstructed from g_sh
// ---------------------------------------------------------------------------
__global__ void __launch_bounds__(256, 1)
k_deform_mma(const float* __restrict__ offset_w,
             const float* __restrict__ cls_w, const float* __restrict__ cls_b,
             const float* __restrict__ bbox_w, const float* __restrict__ bbox_b,
             float* __restrict__ out) {
    extern __shared__ __align__(128) char smem[];
    __half* Asm0 = (__half*)(smem + SM_A0);
    __half* Asm1 = (__half*)(smem + SM_A1);
    __half* Bsm0 = (__half*)(smem + SM_B0);
    __half* Bsm1 = (__half*)(smem + SM_B1);
    float*  red  = (float*)(smem + SM_RED);
    float*  owsm = (float*)(smem + SM_OW);

    const int tid = threadIdx.x, wid = tid >> 5, lane = tid & 31;
    const int g = lane >> 2, t = lane & 3;
    const int wm = wid & 1, wn = wid >> 1;

    const int tt = blockIdx.x;
    const int b  = blockIdx.y;
    const int y0 = (tt / 6) * 8, x0 = (tt % 6) * 16;

    const int pB = tid >> 2, qS = tid & 3;
    int   yP[2], xP[2], pixb[2];
    #pragma unroll
    for (int ph = 0; ph < 2; ++ph) {
        const int pS = ph*64 + pB;
        yP[ph] = y0 + (pS >> 4);
        xP[ph] = x0 + (pS & 15);
        pixb[ph] = (b*Hn + yP[ph])*Wn + xP[ph];
    }

    // cache offset_w (72x2 floats) in smem
    if (tid < 144) owsm[tid] = offset_w[tid];
    __syncthreads();

    // per-pixel shape values
    float2 shv[2];
    shv[0] = *(const float2*)&g_sh[((size_t)pixb[0])*2];
    shv[1] = *(const float2*)&g_sh[((size_t)pixb[1])*2];

    float d[4][8][4];
    #pragma unroll
    for (int i = 0; i < 4; ++i)
        #pragma unroll
        for (int j = 0; j < 8; ++j)
            #pragma unroll
            for (int k = 0; k < 4; ++k) d[i][j][k] = 0.f;

    const uint32_t dbOff = (uint32_t)(tid*LDBh)*2;
    const uint32_t db0 = smem_u32(Bsm0) + dbOff, db1 = smem_u32(Bsm1) + dbOff;

    int    ga[2][4];
    float  gw[2][4];
    uint4  u[4];

    auto calc_meta = [&](int gt) {
        const int gg = gt / 9, tap = gt - gg*9;
        const int dy = tap/3 - 1, dx = tap%3 - 1;
        const float w00 = owsm[4*gt + 0], w01 = owsm[4*gt + 1];
        const float w10 = owsm[4*gt + 2], w11 = owsm[4*gt + 3];
        #pragma unroll
        for (int ph = 0; ph < 2; ++ph) {
            const float offy = shv[ph].x*w00 + shv[ph].y*w01;
            const float offx = shv[ph].x*w10 + shv[ph].y*w11;
            const float pyf = (float)(yP[ph] + dy) + offy;
            const float pxf = (float)(xP[ph] + dx) + offx;
            const float y0f = floorf(pyf), x0f = floorf(pxf);
            const float wy = pyf - y0f, wx = pxf - x0f;
            const int yi = (int)y0f, xi = (int)x0f;
            #pragma unroll
            for (int cy = 0; cy < 2; ++cy)
                #pragma unroll
                for (int cx = 0; cx < 2; ++cx) {
                    const int k = cy*2 + cx;
                    const int yc = yi + cy, xc = xi + cx;
                    const bool valid = (yc >= 0 && yc < Hn && xc >= 0 && xc < Wn);
                    const int ycc = min(max(yc, 0), Hn - 1);
                    const int xcc = min(max(xc, 0), Wn - 1);
                    const float wv = (cy ? wy : 1.f - wy) * (cx ? wx : 1.f - wx);
                    gw[ph][k] = valid ? wv : 0.f;
                    ga[ph][k] = ((b*Hn + ycc)*Wn + xcc)*Cn + gg*CGn;
                }
        }
    };

#define GATHER_SUB(cc, ph) {                                                   \
    const int _chb = ((cc) & 1)*32 + qS*8;                                     \
    u[0] = *(const uint4*)&g_t[(size_t)ga[ph][0] + _chb];                      \
    u[1] = *(const uint4*)&g_t[(size_t)ga[ph][1] + _chb];                      \
    u[2] = *(const uint4*)&g_t[(size_t)ga[ph][2] + _chb];                      \
    u[3] = *(const uint4*)&g_t[(size_t)ga[ph][3] + _chb];                      \
}
#define COMBINE_STS(ph, Abuf) {                                                \
    float r[8];                                                                \
    _Pragma("unroll")                                                          \
    for (int j = 0; j < 8; ++j) r[j] = 0.f;                                    \
    _Pragma("unroll")                                                          \
    for (int k = 0; k < 4; ++k) {                                              \
        const __half2* h = (const __half2*)&u[k];                              \
        const float w = gw[ph][k];                                             \
        _Pragma("unroll")                                                      \
        for (int j = 0; j < 4; ++j) {                                          \
            const float2 v = __half22float2(h[j]);                             \
            r[2*j]   += w * v.x;                                               \
            r[2*j+1] += w * v.y;                                               \
        }                                                                      \
    }                                                                          \
    __half2 o[4];                                                              \
    _Pragma("unroll")                                                          \
    for (int j = 0; j < 4; ++j) o[j] = __floats2half2_rn(r[2*j], r[2*j+1]);    \
    *(uint4*)&(Abuf)[((ph)*64 + pB)*LDAh + qS*8] = *(uint4*)o;                 \
}
#define STAGE_B(cc, db) {                                                      \
    const __half* ws = &g_w2h[(size_t)(cc)*8192 + tid*32];                     \
    _Pragma("unroll")                                                          \
    for (int q = 0; q < 4; ++q) CPA16((db) + q*16, ws + q*8);                  \
    CPA_COMMIT();                                                              \
}
#define DEFORM_STEP(AX, BX, cn, AY, dbY, hasnext) {                            \
    if (hasnext) { STAGE_B(cn, dbY); GATHER_SUB(cn, 0); }                      \
    MMA_KSTEP(AX, BX, 0)                                                       \
    if (hasnext) { COMBINE_STS(0, AY); GATHER_SUB(cn, 1); }                    \
    MMA_KSTEP(AX, BX, 1)                                                       \
    if (hasnext) { COMBINE_STS(1, AY); }                                       \
    CPA_WAIT0();                                                               \
    __syncthreads();                                                           \
}

    // prologue: meta gt0, stage chunk 0 -> buf0
    calc_meta(0);
    STAGE_B(0, db0);
    GATHER_SUB(0, 0); COMBINE_STS(0, Asm0);
    GATHER_SUB(0, 1); COMBINE_STS(1, Asm0);
    CPA_WAIT0();
    __syncthreads();

    #pragma unroll 1
    for (int c = 0; c < NCHUNK; c += 2) {
        DEFORM_STEP(Asm0, Bsm0, c + 1, Asm1, db1, (c + 1 < NCHUNK))
        if (c + 2 < NCHUNK) calc_meta((c + 2) >> 1);
        DEFORM_STEP(Asm1, Bsm1, c + 2, Asm0, db0, (c + 2 < NCHUNK))
    }

    // ---- epilogue: relu + cls/bbox head partials -----------------------
    float P[5][8];
    #pragma unroll
    for (int h = 0; h < 5; ++h)
        #pragma unroll
        for (int s = 0; s < 8; ++s) P[h][s] = 0.f;

    #pragma unroll
    for (int ma = 0; ma < 4; ++ma)
        #pragma unroll
        for (int na = 0; na < 8; ++na)
            #pragma unroll
            for (int ci = 0; ci < 4; ++ci) {
                const int oc = wn*64 + na*8 + 2*t + (ci & 1);
                const int slot = ma*2 + (ci >> 1);
                const float v = fmaxf(d[ma][na][ci], 0.f);
                P[0][slot] += v * cls_w[oc];
                P[1][slot] += v * bbox_w[oc];
                P[2][slot] += v * bbox_w[Cn + oc];
                P[3][slot] += v * bbox_w[2*Cn + oc];
                P[4][slot] += v * bbox_w[3*Cn + oc];
            }
    #pragma unroll
    for (int h = 0; h < 5; ++h)
        #pragma unroll
        for (int s = 0; s < 8; ++s) {
            P[h][s] += __shfl_xor_sync(0xffffffffu, P[h][s], 1);
            P[h][s] += __shfl_xor_sync(0xffffffffu, P[h][s], 2);
        }
    if (t == 0) {
        #pragma unroll
        for (int s = 0; s < 8; ++s) {
            const int row = wm*64 + (s >> 1)*16 + g + (s & 1)*8;
            #pragma unroll
            for (int h = 0; h < 5; ++h)
                red[h*512 + row*4 + wn] = P[h][s];
        }
    }
    __syncthreads();

    if (tid < 128) {
        const int px = tid;
        float s[5] = {0.f, 0.f, 0.f, 0.f, 0.f};
        #pragma unroll
        for (int h = 0; h < 5; ++h)
            #pragma unroll
            for (int w = 0; w < 4; ++w)
                s[h] += red[h*512 + px*4 + w];
        const int y = y0 + (px >> 4), xg = x0 + (px & 15);
        const int pix = y*Wn + xg;
        out[OUT_LOGITS + b*HW + pix]        = s[0] + cls_b[0];
        out[OUT_BBOX + (b*4 + 0)*HW + pix]  = s[1] + bbox_b[0];
        out[OUT_BBOX + (b*4 + 1)*HW + pix]  = s[2] + bbox_b[1];
        out[OUT_BBOX + (b*4 + 2)*HW + pix]  = s[3] + bbox_b[2];
        out[OUT_BBOX + (b*4 + 3)*HW + pix]  = s[4] + bbox_b[3];
    }
}

// ---------------------------------------------------------------------------
extern "C" void kernel_launch(void* const* d_in, const int* in_sizes, int n_in,
                              void* d_out, int out_size) {
    const float* feature  = (const float*)d_in[0];
    const float* conv_w   = (const float*)d_in[1];
    const float* conv_b   = (const float*)d_in[2];
    const float* loc_w    = (const float*)d_in[3];
    const float* loc_b    = (const float*)d_in[4];
    const float* shape_w  = (const float*)d_in[5];
    const float* shape_b  = (const float*)d_in[6];
    const float* offset_w = (const float*)d_in[7];
    const float* adapt_w  = (const float*)d_in[8];
    const float* cls_w    = (const float*)d_in[9];
    const float* cls_b    = (const float*)d_in[10];
    const float* bbox_w   = (const float*)d_in[11];
    const float* bbox_b   = (const float*)d_in[12];
    float* out = (float*)d_out;

    cudaFuncSetAttribute(k_conv1_mma,
        cudaFuncAttributeMaxDynamicSharedMemorySize, C1TOTAL);
    cudaFuncSetAttribute(k_deform_mma,
        cudaFuncAttributeMaxDynamicSharedMemorySize, SM_TOTAL);

    k_prep_all<<<9216, 256>>>(feature, conv_w, adapt_w);
    k_conv1_mma<<<dim3(72, Bn), 256, C1TOTAL>>>(conv_b, loc_w, loc_b,
                                                shape_w, shape_b, out);
    k_deform_mma<<<dim3(72, Bn), 256, SM_TOTAL>>>(offset_w, cls_w, cls_b,
                                                  bbox_w, bbox_b, out);
}

// round 17
// speedup vs baseline: 1.2419x; 1.0539x over previous
#include <cuda_runtime.h>
#include <cuda_fp16.h>
#include <math.h>
#include <stdint.h>

// Problem constants
#define Bn 2
#define Cn 256
#define Hn 96
#define Wn 96
#define HW (Hn*Wn)
#define CGn 64
#define KKn 9
#define KTOT 2304
#define NCHUNK 72           // K chunks of 32

// Output layout
#define OUT_LOGITS 0
#define OUT_BBOX   18432
#define OUT_SHAPE  92160
#define OUT_LOC    129024

// smem strides in HALVES — 40: conflict-free fragment loads (R10-proven)
#define LDAh 40
#define LDBh 40

// ---- conv1 smem layout: 4-deep pipeline (R13) ----
#define C1A0  0              // 128*40*2 = 10240 each
#define C1A1  10240
#define C1A2  20480
#define C1A3  30720
#define C1B0  40960          // 256*40*2 = 20480 each
#define C1B1  61440
#define C1B2  81920
#define C1B3  102400
#define C1RED 122880         // 3*512*4 = 6144
#define C1TOTAL 129024

// ---- deform smem layout: 4 A bufs + 4 B bufs, sync per 2 chunks ----
#define D_A0   0             // 128*40*2 = 10240 each
#define D_A1   10240
#define D_A2   20480
#define D_A3   30720
#define D_B0   40960         // 256*40*2 = 20480 each
#define D_B1   61440
#define D_B2   81920
#define D_B3   102400
#define D_RED  122880        // 5*512*4 = 10240
#define D_OW   133120        // 144*4 = 576
#define D_TOTAL 133696

// Scratch (device globals)
__device__ __half g_x  [Bn*HW*Cn];     // feature NHWC, fp16
__device__ __half g_t  [Bn*HW*Cn];     // conv1 output NHWC, fp16
__device__ float  g_sh [Bn*HW*2];      // shape_pred per pixel (s0,s1)
__device__ __half g_w1h[KTOT*Cn];      // [chunk][oc][32], fp16
__device__ __half g_w2h[KTOT*Cn];

// ---------------- helpers ---------------------------------------------------
__device__ __forceinline__ uint32_t smem_u32(const void* p) {
    uint32_t a;
    asm("{ .reg .u64 t; cvta.to.shared.u64 t, %1; cvt.u32.u64 %0, t; }"
        : "=r"(a) : "l"(p));
    return a;
}
__device__ __forceinline__ void mma16(float* d, const uint32_t* a,
                                      uint32_t b0, uint32_t b1) {
    asm volatile(
        "mma.sync.aligned.m16n8k16.row.col.f32.f16.f16.f32 "
        "{%0,%1,%2,%3},{%4,%5,%6,%7},{%8,%9},{%0,%1,%2,%3};"
        : "+f"(d[0]), "+f"(d[1]), "+f"(d[2]), "+f"(d[3])
        : "r"(a[0]), "r"(a[1]), "r"(a[2]), "r"(a[3]), "r"(b0), "r"(b1));
}
#define CPA16(dst, src) \
    asm volatile("cp.async.ca.shared.global [%0], [%1], 16;" \
                 :: "r"(dst), "l"(src))
#define CPA16Z(dst, src, n) \
    asm volatile("cp.async.ca.shared.global [%0], [%1], 16, %2;" \
                 :: "r"(dst), "l"(src), "r"(n))
#define CPA_COMMIT() asm volatile("cp.async.commit_group;")
#define CPA_WAIT0()  asm volatile("cp.async.wait_group 0;")
#define CPA_WAIT2()  asm volatile("cp.async.wait_group 2;")

// ---------------------------------------------------------------------------
// Kernel 1: merged prep — transpose feature + weight re-layout (R16 WIN)
// ---------------------------------------------------------------------------
__global__ void k_prep_all(const float* __restrict__ x,
                           const float* __restrict__ conv_w,
                           const float* __restrict__ adapt_w) {
    __shared__ float tile[32][33];
    const int tid = threadIdx.x;
    if (blockIdx.x < 4608) {
        const int bid = blockIdx.x;
        const int b  = bid / 2304;
        const int r  = bid % 2304;
        const int p0 = (r >> 3) * 32;
        const int c0 = (r & 7) * 32;
        const int txi = tid & 31, tyi = tid >> 5;
        #pragma unroll
        for (int s = 0; s < 32; s += 8)
            tile[tyi + s][txi] = x[(size_t)(b*Cn + c0 + tyi + s)*HW + p0 + txi];
        __syncthreads();
        #pragma unroll
        for (int s = 0; s < 32; s += 8)
            g_x[(size_t)(b*HW + p0 + tyi + s)*Cn + c0 + txi] =
                __float2half(tile[txi][tyi + s]);
    } else {
        const int n = KTOT*Cn;
        int idx = (blockIdx.x - 4608) * 256 + tid;
        if (idx < n) {
            int dk = idx & 31;
            int o  = (idx >> 5) & 255;
            int ch = idx >> 13;
            int tap = ch >> 3;
            int c   = (ch & 7)*32 + dk;
            g_w1h[idx] = __float2half(conv_w[(o*Cn + c)*KKn + tap]);
        } else if (idx < 2*n) {
            int j  = idx - n;
            int dk = j & 31;
            int o  = (j >> 5) & 255;
            int ch = j >> 13;
            int gt = ch >> 1;
            int ci = (ch & 1)*32 + dk;
            int g  = gt / 9, tap = gt % 9;
            g_w2h[j] = __float2half(adapt_w[(o*Cn + g*CGn + ci)*KKn + tap]);
        }
    }
}

// One k16-step, 128px tile (warp 64px x 64oc)
#define MMA_KSTEP(Abuf, Bbuf, ks) {                                            \
    const int k0 = (ks)*16;                                                    \
    uint32_t a[4][4];                                                          \
    _Pragma("unroll")                                                          \
    for (int ma = 0; ma < 4; ++ma) {                                           \
        const __half* ap = &(Abuf)[(wm*64 + ma*16 + g)*LDAh + k0 + 2*t];       \
        a[ma][0] = *(const uint32_t*)(ap);                                     \
        a[ma][1] = *(const uint32_t*)(ap + 8*LDAh);                            \
        a[ma][2] = *(const uint32_t*)(ap + 8);                                 \
        a[ma][3] = *(const uint32_t*)(ap + 8*LDAh + 8);                        \
    }                                                                          \
    _Pragma("unroll")                                                          \
    for (int na = 0; na < 8; ++na) {                                           \
        const __half* bp = &(Bbuf)[(wn*64 + na*8 + g)*LDBh + k0 + 2*t];        \
        const uint32_t b0 = *(const uint32_t*)(bp);                            \
        const uint32_t b1 = *(const uint32_t*)(bp + 8);                        \
        mma16(d[0][na], a[0], b0, b1);                                         \
        mma16(d[1][na], a[1], b0, b1);                                         \
        mma16(d[2][na], a[2], b0, b1);                                         \
        mma16(d[3][na], a[3], b0, b1);                                         \
    }                                                                          \
}

#define MMA_CHUNK(Abuf, Bbuf) MMA_KSTEP(Abuf, Bbuf, 0) MMA_KSTEP(Abuf, Bbuf, 1)

// ---------------------------------------------------------------------------
// Kernel 3: conv3x3 via mma.sync fp16, 4-deep cp.async pipeline (R13/R16 WIN)
// ---------------------------------------------------------------------------
__global__ void __launch_bounds__(256, 1)
k_conv1_mma(const float* __restrict__ conv_b_,
            const float* __restrict__ loc_w,  const float* __restrict__ loc_b,
            const float* __restrict__ shape_w,const float* __restrict__ shape_b,
            float* __restrict__ out) {
    extern __shared__ __align__(128) char smem[];
    __half* AsmP[4] = {(__half*)(smem + C1A0), (__half*)(smem + C1A1),
                       (__half*)(smem + C1A2), (__half*)(smem + C1A3)};
    __half* BsmP[4] = {(__half*)(smem + C1B0), (__half*)(smem + C1B1),
                       (__half*)(smem + C1B2), (__half*)(smem + C1B3)};
    float*  red  = (float*)(smem + C1RED);

    const int tid = threadIdx.x, wid = tid >> 5, lane = tid & 31;
    const int g = lane >> 2, t = lane & 3;
    const int wm = wid & 1, wn = wid >> 1;

    const int tt = blockIdx.x;
    const int b  = blockIdx.y;
    const int y0 = (tt / 6) * 8, x0 = (tt % 6) * 16;

    const int pB = tid >> 2, qS = tid & 3;

    float d[4][8][4];
    #pragma unroll
    for (int i = 0; i < 4; ++i)
        #pragma unroll
        for (int j = 0; j < 8; ++j)
            #pragma unroll
            for (int k = 0; k < 4; ++k) d[i][j][k] = 0.f;

    const uint32_t daOff = (uint32_t)(pB*LDAh + qS*8)*2;
    const uint32_t dbOff = (uint32_t)(tid*LDBh)*2;
    const uint32_t daP[4] = {smem_u32(AsmP[0]) + daOff, smem_u32(AsmP[1]) + daOff,
                             smem_u32(AsmP[2]) + daOff, smem_u32(AsmP[3]) + daOff};
    const uint32_t dbP[4] = {smem_u32(BsmP[0]) + dbOff, smem_u32(BsmP[1]) + dbOff,
                             smem_u32(BsmP[2]) + dbOff, smem_u32(BsmP[3]) + dbOff};

    auto stage = [&](int c, uint32_t da, uint32_t db) {
        const int tap = c >> 3, cin0 = (c & 7) << 5;
        const int dy = tap/3 - 1, dx = tap%3 - 1;
        #pragma unroll
        for (int ph = 0; ph < 2; ++ph) {
            const int pS = ph*64 + pB;
            const int yy = y0 + (pS >> 4) + dy, xx = x0 + (pS & 15) + dx;
            const bool ok = (yy >= 0 && yy < Hn && xx >= 0 && xx < Wn);
            const __half* src = ok
                ? &g_x[((size_t)((b*Hn + yy)*Wn + xx))*Cn + cin0 + qS*8] : g_x;
            const uint32_t nb = ok ? 16u : 0u;
            CPA16Z(da + (uint32_t)(ph*64*LDAh)*2, src, nb);
        }
        const __half* ws = &g_w1h[(size_t)c*8192 + tid*32];
        #pragma unroll
        for (int q = 0; q < 4; ++q) CPA16(db + q*16, ws + q*8);
        CPA_COMMIT();
    };

    stage(0, daP[0], dbP[0]);
    stage(1, daP[1], dbP[1]);
    stage(2, daP[2], dbP[2]);

    #pragma unroll 1
    for (int c = 0; c < NCHUNK; c += 4) {
        CPA_WAIT2(); __syncthreads();
        MMA_CHUNK(AsmP[0], BsmP[0]);
        if (c + 3 < NCHUNK) stage(c + 3, daP[3], dbP[3]);

        CPA_WAIT2(); __syncthreads();
        MMA_CHUNK(AsmP[1], BsmP[1]);
        if (c + 4 < NCHUNK) stage(c + 4, daP[0], dbP[0]);

        CPA_WAIT2(); __syncthreads();
        MMA_CHUNK(AsmP[2], BsmP[2]);
        if (c + 5 < NCHUNK) stage(c + 5, daP[1], dbP[1]);

        CPA_WAIT2(); __syncthreads();
        MMA_CHUNK(AsmP[3], BsmP[3]);
        if (c + 6 < NCHUNK) stage(c + 6, daP[2], dbP[2]);
    }
    __syncthreads();

    // ---- epilogue: bias + relu, heads, g_t ----
    float P0[8], P1[8], P2[8];
    #pragma unroll
    for (int s = 0; s < 8; ++s) { P0[s] = 0.f; P1[s] = 0.f; P2[s] = 0.f; }

    #pragma unroll
    for (int ma = 0; ma < 4; ++ma)
        #pragma unroll
        for (int na = 0; na < 8; ++na)
            #pragma unroll
            for (int ci = 0; ci < 4; ++ci) {
                const int oc = wn*64 + na*8 + 2*t + (ci & 1);
                const int slot = ma*2 + (ci >> 1);
                float v = fmaxf(d[ma][na][ci] + conv_b_[oc], 0.f);
                d[ma][na][ci] = v;
                P0[slot] += v * loc_w[oc];
                P1[slot] += v * shape_w[oc];
                P2[slot] += v * shape_w[Cn + oc];
            }
    #pragma unroll
    for (int s = 0; s < 8; ++s) {
        P0[s] += __shfl_xor_sync(0xffffffffu, P0[s], 1);
        P0[s] += __shfl_xor_sync(0xffffffffu, P0[s], 2);
        P1[s] += __shfl_xor_sync(0xffffffffu, P1[s], 1);
        P1[s] += __shfl_xor_sync(0xffffffffu, P1[s], 2);
        P2[s] += __shfl_xor_sync(0xffffffffu, P2[s], 2);
        P2[s] += __shfl_xor_sync(0xffffffffu, P2[s], 1);
    }
    if (t == 0) {
        #pragma unroll
        for (int s = 0; s < 8; ++s) {
            const int row = wm*64 + (s >> 1)*16 + g + (s & 1)*8;
            red[0*512 + row*4 + wn] = P0[s];
            red[1*512 + row*4 + wn] = P1[s];
            red[2*512 + row*4 + wn] = P2[s];
        }
    }
    __syncthreads();

    if (tid < 128) {
        const int px = tid;
        float sl = 0.f, s0 = 0.f, s1 = 0.f;
        #pragma unroll
        for (int w = 0; w < 4; ++w) {
            sl += red[0*512 + px*4 + w];
            s0 += red[1*512 + px*4 + w];
            s1 += red[2*512 + px*4 + w];
        }
        const int y = y0 + (px >> 4), xg = x0 + (px & 15);
        const int pix = y*Wn + xg;
        out[OUT_LOC + b*HW + pix] = sl + loc_b[0];
        const float a0 = s0 + shape_b[0];
        const float a1 = s1 + shape_b[1];
        out[OUT_SHAPE + (b*2 + 0)*HW + pix] = a0;
        out[OUT_SHAPE + (b*2 + 1)*HW + pix] = a1;
        *(float2*)&g_sh[((size_t)(b*HW + pix))*2] = make_float2(a0, a1);
    }

    // g_t: direct scattered half2 stores from accumulators
    #pragma unroll
    for (int ma = 0; ma < 4; ++ma) {
        const int row0 = wm*64 + ma*16 + g;
        const int pix0 = (b*Hn + y0 + (row0 >> 4))*Wn + x0 + (row0 & 15);
        const int row1 = row0 + 8;
        const int pix1 = (b*Hn + y0 + (row1 >> 4))*Wn + x0 + (row1 & 15);
        #pragma unroll
        for (int na = 0; na < 8; ++na) {
            const int col = wn*64 + na*8 + 2*t;
            *(__half2*)&g_t[(size_t)pix0*Cn + col] =
                __floats2half2_rn(d[ma][na][0], d[ma][na][1]);
            *(__half2*)&g_t[(size_t)pix1*Cn + col] =
                __floats2half2_rn(d[ma][na][2], d[ma][na][3]);
        }
    }
}

// ---------------------------------------------------------------------------
// Kernel 4: deformable conv, 4-buffer pipeline, sync per 2 chunks
// ---------------------------------------------------------------------------
__global__ void __launch_bounds__(256, 1)
k_deform_mma(const float* __restrict__ offset_w,
             const float* __restrict__ cls_w, const float* __restrict__ cls_b,
             const float* __restrict__ bbox_w, const float* __restrict__ bbox_b,
             float* __restrict__ out) {
    extern __shared__ __align__(128) char smem[];
    __half* Asm0 = (__half*)(smem + D_A0);
    __half* Asm1 = (__half*)(smem + D_A1);
    __half* Asm2 = (__half*)(smem + D_A2);
    __half* Asm3 = (__half*)(smem + D_A3);
    __half* Bsm0 = (__half*)(smem + D_B0);
    __half* Bsm1 = (__half*)(smem + D_B1);
    __half* Bsm2 = (__half*)(smem + D_B2);
    __half* Bsm3 = (__half*)(smem + D_B3);
    float*  red  = (float*)(smem + D_RED);
    float*  owsm = (float*)(smem + D_OW);

    const int tid = threadIdx.x, wid = tid >> 5, lane = tid & 31;
    const int g = lane >> 2, t = lane & 3;
    const int wm = wid & 1, wn = wid >> 1;

    const int tt = blockIdx.x;
    const int b  = blockIdx.y;
    const int y0 = (tt / 6) * 8, x0 = (tt % 6) * 16;

    const int pB = tid >> 2, qS = tid & 3;
    int   yP[2], xP[2], pixb[2];
    #pragma unroll
    for (int ph = 0; ph < 2; ++ph) {
        const int pS = ph*64 + pB;
        yP[ph] = y0 + (pS >> 4);
        xP[ph] = x0 + (pS & 15);
        pixb[ph] = (b*Hn + yP[ph])*Wn + xP[ph];
    }

    if (tid < 144) owsm[tid] = offset_w[tid];
    __syncthreads();

    float2 shv[2];
    shv[0] = *(const float2*)&g_sh[((size_t)pixb[0])*2];
    shv[1] = *(const float2*)&g_sh[((size_t)pixb[1])*2];

    float d[4][8][4];
    #pragma unroll
    for (int i = 0; i < 4; ++i)
        #pragma unroll
        for (int j = 0; j < 8; ++j)
            #pragma unroll
            for (int k = 0; k < 4; ++k) d[i][j][k] = 0.f;

    const uint32_t dbOff = (uint32_t)(tid*LDBh)*2;
    const uint32_t db0 = smem_u32(Bsm0) + dbOff, db1 = smem_u32(Bsm1) + dbOff;
    const uint32_t db2 = smem_u32(Bsm2) + dbOff, db3 = smem_u32(Bsm3) + dbOff;

    int    ga[2][4];
    float  gw[2][4];
    uint4  u[4];

    auto calc_meta = [&](int gt) {
        const int gg = gt / 9, tap = gt - gg*9;
        const int dy = tap/3 - 1, dx = tap%3 - 1;
        const float w00 = owsm[4*gt + 0], w01 = owsm[4*gt + 1];
        const float w10 = owsm[4*gt + 2], w11 = owsm[4*gt + 3];
        #pragma unroll
        for (int ph = 0; ph < 2; ++ph) {
            const float offy = shv[ph].x*w00 + shv[ph].y*w01;
            const float offx = shv[ph].x*w10 + shv[ph].y*w11;
            const float pyf = (float)(yP[ph] + dy) + offy;
            const float pxf = (float)(xP[ph] + dx) + offx;
            const float y0f = floorf(pyf), x0f = floorf(pxf);
            const float wy = pyf - y0f, wx = pxf - x0f;
            const int yi = (int)y0f, xi = (int)x0f;
            #pragma unroll
            for (int cy = 0; cy < 2; ++cy)
                #pragma unroll
                for (int cx = 0; cx < 2; ++cx) {
                    const int k = cy*2 + cx;
                    const int yc = yi + cy, xc = xi + cx;
                    const bool valid = (yc >= 0 && yc < Hn && xc >= 0 && xc < Wn);
                    const int ycc = min(max(yc, 0), Hn - 1);
                    const int xcc = min(max(xc, 0), Wn - 1);
                    const float wv = (cy ? wy : 1.f - wy) * (cx ? wx : 1.f - wx);
                    gw[ph][k] = valid ? wv : 0.f;
                    ga[ph][k] = ((b*Hn + ycc)*Wn + xcc)*Cn + gg*CGn;
                }
        }
    };

#define GATHER_SUB(cc, ph) {                                                   \
    const int _chb = ((cc) & 1)*32 + qS*8;                                     \
    u[0] = *(const uint4*)&g_t[(size_t)ga[ph][0] + _chb];                      \
    u[1] = *(const uint4*)&g_t[(size_t)ga[ph][1] + _chb];                      \
    u[2] = *(const uint4*)&g_t[(size_t)ga[ph][2] + _chb];                      \
    u[3] = *(const uint4*)&g_t[(size_t)ga[ph][3] + _chb];                      \
}
#define COMBINE_STS(ph, Abuf) {                                                \
    float r[8];                                                                \
    _Pragma("unroll")                                                          \
    for (int j = 0; j < 8; ++j) r[j] = 0.f;                                    \
    _Pragma("unroll")                                                          \
    for (int k = 0; k < 4; ++k) {                                              \
        const __half2* h = (const __half2*)&u[k];                              \
        const float w = gw[ph][k];                                             \
        _Pragma("unroll")                                                      \
        for (int j = 0; j < 4; ++j) {                                          \
            const float2 v = __half22float2(h[j]);                             \
            r[2*j]   += w * v.x;                                               \
            r[2*j+1] += w * v.y;                                               \
        }                                                                      \
    }                                                                          \
    __half2 o[4];                                                              \
    _Pragma("unroll")                                                          \
    for (int j = 0; j < 4; ++j) o[j] = __floats2half2_rn(r[2*j], r[2*j+1]);    \
    *(uint4*)&(Abuf)[((ph)*64 + pB)*LDAh + qS*8] = *(uint4*)o;                 \
}
#define STAGE_B(cc, db) {                                                      \
    const __half* ws = &g_w2h[(size_t)(cc)*8192 + tid*32];                     \
    _Pragma("unroll")                                                          \
    for (int q = 0; q < 4; ++q) CPA16((db) + q*16, ws + q*8);                  \
    CPA_COMMIT();                                                              \
}
// MMA chunks n-2pair from (AX0,BX0),(AX1,BX1) while staging n0,n1 (same gt)
// into (AY0,dbY0),(AY1,dbY1). One wait+sync per 2 chunks.
#define STEP2(AX0, BX0, AX1, BX1, n0, AY0, dbY0, AY1, dbY1) {                  \
    const bool h0 = ((n0) < NCHUNK);                                           \
    if (h0) { calc_meta((n0) >> 1); STAGE_B(n0, dbY0); GATHER_SUB(n0, 0); }    \
    MMA_KSTEP(AX0, BX0, 0)                                                     \
    if (h0) { COMBINE_STS(0, AY0); GATHER_SUB(n0, 1); }                        \
    MMA_KSTEP(AX0, BX0, 1)                                                     \
    if (h0) { COMBINE_STS(1, AY0); STAGE_B((n0)+1, dbY1); GATHER_SUB((n0)+1, 0); } \
    MMA_KSTEP(AX1, BX1, 0)                                                     \
    if (h0) { COMBINE_STS(0, AY1); GATHER_SUB((n0)+1, 1); }                    \
    MMA_KSTEP(AX1, BX1, 1)                                                     \
    if (h0) { COMBINE_STS(1, AY1); }                                           \
    CPA_WAIT0();                                                               \
    __syncthreads();                                                           \
}

    // ---- prologue: chunks 0,1 (gt 0) into pair 0 ----
    calc_meta(0);
    STAGE_B(0, db0);
    GATHER_SUB(0, 0); COMBINE_STS(0, Asm0);
    GATHER_SUB(0, 1); COMBINE_STS(1, Asm0);
    STAGE_B(1, db1);
    GATHER_SUB(1, 0); COMBINE_STS(0, Asm1);
    GATHER_SUB(1, 1); COMBINE_STS(1, Asm1);
    CPA_WAIT0();
    __syncthreads();

    #pragma unroll 1
    for (int c = 0; c < NCHUNK; c += 4) {
        // chunks c,c+1 from pair0; stage c+2,c+3 into pair1
        STEP2(Asm0, Bsm0, Asm1, Bsm1, c + 2, Asm2, db2, Asm3, db3)
        // chunks c+2,c+3 from pair1; stage c+4,c+5 into pair0
        STEP2(Asm2, Bsm2, Asm3, Bsm3, c + 4, Asm0, db0, Asm1, db1)
    }

    // ---- epilogue: relu + cls/bbox head partials -----------------------
    float P[5][8];
    #pragma unroll
    for (int h = 0; h < 5; ++h)
        #pragma unroll
        for (int s = 0; s < 8; ++s) P[h][s] = 0.f;

    #pragma unroll
    for (int ma = 0; ma < 4; ++ma)
        #pragma unroll
        for (int na = 0; na < 8; ++na)
            #pragma unroll
            for (int ci = 0; ci < 4; ++ci) {
                const int oc = wn*64 + na*8 + 2*t + (ci & 1);
                const int slot = ma*2 + (ci >> 1);
                const float v = fmaxf(d[ma][na][ci], 0.f);
                P[0][slot] += v * cls_w[oc];
                P[1][slot] += v * bbox_w[oc];
                P[2][slot] += v * bbox_w[Cn + oc];
                P[3][slot] += v * bbox_w[2*Cn + oc];
                P[4][slot] += v * bbox_w[3*Cn + oc];
            }
    #pragma unroll
    for (int h = 0; h < 5; ++h)
        #pragma unroll
        for (int s = 0; s < 8; ++s) {
            P[h][s] += __shfl_xor_sync(0xffffffffu, P[h][s], 1);
            P[h][s] += __shfl_xor_sync(0xffffffffu, P[h][s], 2);
        }
    if (t == 0) {
        #pragma unroll
        for (int s = 0; s < 8; ++s) {
            const int row = wm*64 + (s >> 1)*16 + g + (s & 1)*8;
            #pragma unroll
            for (int h = 0; h < 5; ++h)
                red[h*512 + row*4 + wn] = P[h][s];
        }
    }
    __syncthreads();

    if (tid < 128) {
        const int px = tid;
        float s[5] = {0.f, 0.f, 0.f, 0.f, 0.f};
        #pragma unroll
        for (int h = 0; h < 5; ++h)
            #pragma unroll
            for (int w = 0; w < 4; ++w)
                s[h] += red[h*512 + px*4 + w];
        const int y = y0 + (px >> 4), xg = x0 + (px & 15);
        const int pix = y*Wn + xg;
        out[OUT_LOGITS + b*HW + pix]        = s[0] + cls_b[0];
        out[OUT_BBOX + (b*4 + 0)*HW + pix]  = s[1] + bbox_b[0];
        out[OUT_BBOX + (b*4 + 1)*HW + pix]  = s[2] + bbox_b[1];
        out[OUT_BBOX + (b*4 + 2)*HW + pix]  = s[3] + bbox_b[2];
        out[OUT_BBOX + (b*4 + 3)*HW + pix]  = s[4] + bbox_b[3];
    }
}

// ---------------------------------------------------------------------------
extern "C" void kernel_launch(void* const* d_in, const int* in_sizes, int n_in,
                              void* d_out, int out_size) {
    const float* feature  = (const float*)d_in[0];
    const float* conv_w   = (const float*)d_in[1];
    const float* conv_b   = (const float*)d_in[2];
    const float* loc_w    = (const float*)d_in[3];
    const float* loc_b    = (const float*)d_in[4];
    const float* shape_w  = (const float*)d_in[5];
    const float* shape_b  = (const float*)d_in[6];
    const float* offset_w = (const float*)d_in[7];
    const float* adapt_w  = (const float*)d_in[8];
    const float* cls_w    = (const float*)d_in[9];
    const float* cls_b    = (const float*)d_in[10];
    const float* bbox_w   = (const float*)d_in[11];
    const float* bbox_b   = (const float*)d_in[12];
    float* out = (float*)d_out;

    cudaFuncSetAttribute(k_conv1_mma,
        cudaFuncAttributeMaxDynamicSharedMemorySize, C1TOTAL);
    cudaFuncSetAttribute(k_deform_mma,
        cudaFuncAttributeMaxDynamicSharedMemorySize, D_TOTAL);

    k_prep_all<<<9216, 256>>>(feature, conv_w, adapt_w);
    k_conv1_mma<<<dim3(72, Bn), 256, C1TOTAL>>>(conv_b, loc_w, loc_b,
                                                shape_w, shape_b, out);
    k_deform_mma<<<dim3(72, Bn), 256, D_TOTAL>>>(offset_w, cls_w, cls_b,
                                                 bbox_w, bbox_b, out);
}